// round 16
// baseline (speedup 1.0000x reference)
#include <cuda_runtime.h>
#include <cuda_fp16.h>
#include <mma.h>
#include <math.h>
#include <stdint.h>

using namespace nvcuda;

#define NMAX 50000
#define EMAX 800000
#define GNUM 64
#define EPSV 1e-5f
#define FINF 3.402823466e38f

// ---------------- scratch (device globals; no allocation allowed) ----------------
__device__ __align__(256) float g_A[NMAX * 64];
__device__ __align__(256) float g_B[NMAX * 64];
__device__ __align__(256) float g_x1[NMAX * 64];
__device__ __align__(256) float g_x2[NMAX * 64];
__device__ __align__(256) int   g_deg[NMAX];
__device__ __align__(256) int   g_off[NMAX + 1];
__device__ __align__(256) int   g_cursor[NMAX];
__device__ __align__(256) int   g_srcs[EMAX];
__device__ __align__(256) int   g_scan[NMAX];
__device__ __align__(256) int   g_blk[64];
__device__ __align__(256) float g_stat[1];
__device__ __align__(256) float g_pool[GNUM * 64];
__device__ __align__(256) float g_cnt[GNUM];
// split-fp16 operand caches
__device__ __align__(256) __half g_haggr[NMAX * 1536];   // per node: hi[768] | lo[768]
__device__ __align__(256) __half g_xh[NMAX * 128];        // per node: hi[64] | lo[64]
__device__ __align__(256) __half g_wh[3 * 2 * 64 * 832];  // per layer: hi[64*832] | lo[64*832]

__device__ __forceinline__ const float* sel_in(int sel, const float* ext) {
    return sel == 0 ? ext : (sel == 1 ? (const float*)g_x1 : (const float*)g_x2);
}

__device__ __forceinline__ void split2(float v, __half& hi, __half& lo) {
    hi = __float2half_rn(v);
    lo = __float2half_rn(v - __half2float(hi));
}

// ---------------- setup kernels ----------------
__global__ void k_zero(int n) {
    int i = blockIdx.x * blockDim.x + threadIdx.x;
    if (i < n) { g_deg[i] = 0; g_cursor[i] = 0; }
    if (i < GNUM * 64) g_pool[i] = 0.f;
    if (i < GNUM) g_cnt[i] = 0.f;
    if (i == 0) { g_stat[0] = 0.f; g_off[0] = 0; }
}

__global__ void k_deg(const int* __restrict__ ei, int E) {
    int e = blockIdx.x * blockDim.x + threadIdx.x;
    if (e >= E) return;
    atomicAdd(&g_deg[ei[E + e]], 1);
}

__global__ void k_scan1(int n) {
    __shared__ int sh[1024];
    int i = blockIdx.x * 1024 + threadIdx.x;
    int v = (i < n) ? g_deg[i] : 0;
    sh[threadIdx.x] = v;
    __syncthreads();
    for (int s = 1; s < 1024; s <<= 1) {
        int t = (threadIdx.x >= s) ? sh[threadIdx.x - s] : 0;
        __syncthreads();
        sh[threadIdx.x] += t;
        __syncthreads();
    }
    if (i < n) g_scan[i] = sh[threadIdx.x];
    if (threadIdx.x == 1023 && blockIdx.x < 64) g_blk[blockIdx.x] = sh[1023];
}

__global__ void k_scan2(int nb) {
    if (threadIdx.x == 0 && blockIdx.x == 0) {
        int run = 0;
        if (nb > 64) nb = 64;
        for (int b = 0; b < nb; b++) { int t = g_blk[b]; g_blk[b] = run; run += t; }
    }
}

__global__ void k_scan3(int n) {
    int i = blockIdx.x * 1024 + threadIdx.x;
    if (i < n) g_off[i + 1] = g_scan[i] + g_blk[blockIdx.x];
}

__global__ void k_csr(const int* __restrict__ ei, int E) {
    int e = blockIdx.x * blockDim.x + threadIdx.x;
    if (e >= E) return;
    int s = ei[e], d = ei[E + e];
    int pos = g_off[d] + atomicAdd(&g_cursor[d], 1);
    g_srcs[pos] = s;
}

__global__ void k_stat(int n) {
    int i = blockIdx.x * blockDim.x + threadIdx.x;
    float v = (i < n) ? logf((float)g_deg[i] + 1.f) : 0.f;
#pragma unroll
    for (int s = 16; s; s >>= 1) v += __shfl_down_sync(0xffffffffu, v, s);
    __shared__ float sh[32];
    if ((threadIdx.x & 31) == 0) sh[threadIdx.x >> 5] = v;
    __syncthreads();
    if (threadIdx.x < 32) {
        float t = (threadIdx.x < (blockDim.x >> 5)) ? sh[threadIdx.x] : 0.f;
#pragma unroll
        for (int s = 16; s; s >>= 1) t += __shfl_down_sync(0xffffffffu, t, s);
        if (threadIdx.x == 0) atomicAdd(g_stat, t);
    }
}

// split external x (layer-0 input) into g_xh
__global__ void k_xsplit(const float* __restrict__ x, int n) {
    int i = blockIdx.x * blockDim.x + threadIdx.x;
    if (i >= n * 64) return;
    int nn = i >> 6, c = i & 63;
    __half h, l; split2(x[i], h, l);
    g_xh[nn * 128 + c] = h;
    g_xh[nn * 128 + 64 + c] = l;
}

// split all 3 layers of post_w into g_wh
__global__ void k_wsplit(const float* __restrict__ pw) {
    int i = blockIdx.x * blockDim.x + threadIdx.x;
    if (i >= 3 * 64 * 832) return;
    int l = i / (64 * 832), r = i % (64 * 832);
    __half h, lo; split2(pw[i], h, lo);
    __half* base = g_wh + (size_t)l * 2 * 64 * 832;
    base[r] = h;
    base[64 * 832 + r] = lo;
}

// ---------------- pre GEMM: A = x@Wi^T + b, B = x@Wj^T ----------------
__global__ __launch_bounds__(128) void k_pre(int insel, const float* __restrict__ ext,
                                             const float* __restrict__ W,
                                             const float* __restrict__ bias, int n) {
    const float* x = sel_in(insel, ext);
    __shared__ float4 xs[32][16];
    int tid = threadIdx.x;
    int o = tid & 63, half_ = tid >> 6;
    const float* wr = W + o * 128 + half_ * 64;
    float w[64];
#pragma unroll
    for (int d = 0; d < 64; d++) w[d] = __ldg(wr + d);
    float bv = half_ ? 0.f : __ldg(bias + o);
    int n0 = blockIdx.x * 32;
#pragma unroll
    for (int i = tid; i < 512; i += 128) {
        int r = i >> 4, c = i & 15, node = n0 + r;
        xs[r][c] = (node < n) ? ((const float4*)x)[node * 16 + c] : make_float4(0.f, 0.f, 0.f, 0.f);
    }
    __syncthreads();
    float* dst = half_ ? g_B : g_A;
#pragma unroll
    for (int nb4 = 0; nb4 < 32; nb4 += 4) {
        float a0 = bv, a1 = bv, a2 = bv, a3 = bv;
#pragma unroll
        for (int c = 0; c < 16; c++) {
            float4 v0 = xs[nb4 + 0][c];
            float4 v1 = xs[nb4 + 1][c];
            float4 v2 = xs[nb4 + 2][c];
            float4 v3 = xs[nb4 + 3][c];
            float w0 = w[4 * c + 0], w1 = w[4 * c + 1], w2 = w[4 * c + 2], w3 = w[4 * c + 3];
            a0 = fmaf(w0, v0.x, a0); a0 = fmaf(w1, v0.y, a0); a0 = fmaf(w2, v0.z, a0); a0 = fmaf(w3, v0.w, a0);
            a1 = fmaf(w0, v1.x, a1); a1 = fmaf(w1, v1.y, a1); a1 = fmaf(w2, v1.z, a1); a1 = fmaf(w3, v1.w, a1);
            a2 = fmaf(w0, v2.x, a2); a2 = fmaf(w1, v2.y, a2); a2 = fmaf(w2, v2.z, a2); a2 = fmaf(w3, v2.w, a2);
            a3 = fmaf(w0, v3.x, a3); a3 = fmaf(w1, v3.y, a3); a3 = fmaf(w2, v3.z, a3); a3 = fmaf(w3, v3.w, a3);
        }
        if (n0 + nb4 + 0 < n) dst[(n0 + nb4 + 0) * 64 + o] = a0;
        if (n0 + nb4 + 1 < n) dst[(n0 + nb4 + 1) * 64 + o] = a1;
        if (n0 + nb4 + 2 < n) dst[(n0 + nb4 + 2) * 64 + o] = a2;
        if (n0 + nb4 + 3 < n) dst[(n0 + nb4 + 3) * 64 + o] = a3;
    }
}

// ---------------- aggregation: warp per node over CSR; emits split fp16 ----------------
__global__ __launch_bounds__(256) void k_aggr(int n) {
    int warp = (blockIdx.x * blockDim.x + threadIdx.x) >> 5;
    int lane = threadIdx.x & 31;
    if (warp >= n) return;
    int s = g_off[warp], e = g_off[warp + 1];
    const float2* B2 = (const float2*)g_B;
    float sx = 0.f, sy = 0.f, qx = 0.f, qy = 0.f;
    float mnx = FINF, mny = FINF, mxx = -FINF, mxy = -FINF;
    int i = s;
    for (; i + 4 <= e; i += 4) {
        int a0 = g_srcs[i], a1 = g_srcs[i + 1], a2 = g_srcs[i + 2], a3 = g_srcs[i + 3];
        float2 v0 = B2[a0 * 32 + lane];
        float2 v1 = B2[a1 * 32 + lane];
        float2 v2 = B2[a2 * 32 + lane];
        float2 v3 = B2[a3 * 32 + lane];
        sx += v0.x; sy += v0.y; qx = fmaf(v0.x, v0.x, qx); qy = fmaf(v0.y, v0.y, qy);
        mnx = fminf(mnx, v0.x); mny = fminf(mny, v0.y); mxx = fmaxf(mxx, v0.x); mxy = fmaxf(mxy, v0.y);
        sx += v1.x; sy += v1.y; qx = fmaf(v1.x, v1.x, qx); qy = fmaf(v1.y, v1.y, qy);
        mnx = fminf(mnx, v1.x); mny = fminf(mny, v1.y); mxx = fmaxf(mxx, v1.x); mxy = fmaxf(mxy, v1.y);
        sx += v2.x; sy += v2.y; qx = fmaf(v2.x, v2.x, qx); qy = fmaf(v2.y, v2.y, qy);
        mnx = fminf(mnx, v2.x); mny = fminf(mny, v2.y); mxx = fmaxf(mxx, v2.x); mxy = fmaxf(mxy, v2.y);
        sx += v3.x; sy += v3.y; qx = fmaf(v3.x, v3.x, qx); qy = fmaf(v3.y, v3.y, qy);
        mnx = fminf(mnx, v3.x); mny = fminf(mny, v3.y); mxx = fmaxf(mxx, v3.x); mxy = fmaxf(mxy, v3.y);
    }
    for (; i < e; i++) {
        int a = g_srcs[i];
        float2 v = B2[a * 32 + lane];
        sx += v.x; sy += v.y; qx = fmaf(v.x, v.x, qx); qy = fmaf(v.y, v.y, qy);
        mnx = fminf(mnx, v.x); mny = fminf(mny, v.y); mxx = fmaxf(mxx, v.x); mxy = fmaxf(mxy, v.y);
    }
    int d = e - s;
    float df = (float)d;
    float degv = (float)max(d, 1);
    float2 c = ((const float2*)g_A)[warp * 32 + lane];
    float S1x = fmaf(df, c.x, sx), S1y = fmaf(df, c.y, sy);
    float S2x = df * c.x * c.x + 2.f * c.x * sx + qx;
    float S2y = df * c.y * c.y + 2.f * c.y * sy + qy;
    float meanx = S1x / degv, meany = S1y / degv;
    float varx = fmaxf(S2x / degv - meanx * meanx, 0.f);
    float vary = fmaxf(S2y / degv - meany * meany, 0.f);
    float stdx = sqrtf(varx + EPSV), stdy = sqrtf(vary + EPSV);
    float mnvx, mnvy, mxvx, mxvy;
    if (d > 0) { mnvx = c.x + mnx; mnvy = c.y + mny; mxvx = c.x + mxx; mxvy = c.y + mxy; }
    else { mnvx = mnvy = mxvx = mxvy = 0.f; }

    float avg = g_stat[0] / (float)n;
    float ld = logf(degv + 1.f);
    float amp = ld / avg, att = avg / ld;

    __half* H = g_haggr + (size_t)warp * 1536;
    float vx[4] = {meanx, mnvx, mxvx, stdx};
    float vy[4] = {meany, mnvy, mxvy, stdy};
#pragma unroll
    for (int s2 = 0; s2 < 4; s2++) {
        int cc0 = s2 * 64 + 2 * lane;
        float sx3[3] = {vx[s2], vx[s2] * amp, vx[s2] * att};
        float sy3[3] = {vy[s2], vy[s2] * amp, vy[s2] * att};
#pragma unroll
        for (int q = 0; q < 3; q++) {
            __half hx, lx, hy, ly;
            split2(sx3[q], hx, lx);
            split2(sy3[q], hy, ly);
            int cc = q * 256 + cc0;
            *(__half2*)(H + cc) = __halves2half2(hx, hy);
            *(__half2*)(H + 768 + cc) = __halves2half2(lx, ly);
        }
    }
}

// ---------------- fused post+lin via wmma split-fp16; staging = pure copy ----------------
__global__ __launch_bounds__(256) void k_postlin(const __half* __restrict__ Wh,
                                                 const float* __restrict__ bias,
                                                 const float* __restrict__ LW,
                                                 const float* __restrict__ lb,
                                                 int outsel, int n) {
    float* xo = (outsel == 1) ? g_x1 : g_x2;
    __shared__ __align__(256) unsigned char smem[36864];
    __half* As_hi = (__half*)(smem);            // [64][40]
    __half* As_lo = (__half*)(smem + 5120);
    __half* Ws_hi = (__half*)(smem + 10240);    // [64][40]
    __half* Ws_lo = (__half*)(smem + 15360);
    __half* lw_hi = (__half*)(smem);            // [64][72] overlay after mainloop
    __half* lw_lo = (__half*)(smem + 9216);
    float*  t32   = (float*)(smem + 20480);     // [64][64]
    __half* t_hi  = (__half*)(smem + 20480);    // overlays t32
    __half* t_lo  = (__half*)(smem + 20480 + 8192);

    int tid = threadIdx.x;
    int w = tid >> 5;
    int mtile = w >> 1;
    int nbase = (w & 1) * 32;
    int bm = blockIdx.x * 64;

    wmma::fragment<wmma::accumulator, 16, 16, 16, float> acc[2];
    wmma::fill_fragment(acc[0], 0.f);
    wmma::fill_fragment(acc[1], 0.f);

    int row = tid >> 2;             // 0..63
    int kq = (tid & 3) * 8;         // 0,8,16,24 (half units)

#pragma unroll 1
    for (int k0 = 0; k0 < 832; k0 += 32) {
        // ---- A: copy pre-split halves ----
        {
            int nn = bm + row;
            uint4 vh = make_uint4(0, 0, 0, 0), vl = make_uint4(0, 0, 0, 0);
            if (nn < n) {
                const __half* sh;
                const __half* sl;
                if (k0 < 64) {
                    sh = g_xh + nn * 128 + k0 + kq;
                    sl = sh + 64;
                } else {
                    int cc = k0 - 64 + kq;
                    sh = g_haggr + (size_t)nn * 1536 + cc;
                    sl = sh + 768;
                }
                vh = *(const uint4*)sh;
                vl = *(const uint4*)sl;
            }
            *(uint4*)(As_hi + row * 40 + kq) = vh;
            *(uint4*)(As_lo + row * 40 + kq) = vl;
        }
        // ---- W: copy pre-split halves ----
        {
            const __half* wh = Wh + row * 832 + k0 + kq;
            *(uint4*)(Ws_hi + row * 40 + kq) = *(const uint4*)wh;
            *(uint4*)(Ws_lo + row * 40 + kq) = *(const uint4*)(wh + 64 * 832);
        }
        __syncthreads();
#pragma unroll
        for (int kk = 0; kk < 32; kk += 16) {
            wmma::fragment<wmma::matrix_a, 16, 16, 16, __half, wmma::row_major> a_hi, a_lo;
            wmma::load_matrix_sync(a_hi, As_hi + mtile * 16 * 40 + kk, 40);
            wmma::load_matrix_sync(a_lo, As_lo + mtile * 16 * 40 + kk, 40);
#pragma unroll
            for (int t = 0; t < 2; t++) {
                int n0 = nbase + t * 16;
                wmma::fragment<wmma::matrix_b, 16, 16, 16, __half, wmma::col_major> b_hi, b_lo;
                wmma::load_matrix_sync(b_hi, Ws_hi + n0 * 40 + kk, 40);
                wmma::load_matrix_sync(b_lo, Ws_lo + n0 * 40 + kk, 40);
                wmma::mma_sync(acc[t], a_hi, b_hi, acc[t]);
                wmma::mma_sync(acc[t], a_hi, b_lo, acc[t]);
                wmma::mma_sync(acc[t], a_lo, b_hi, acc[t]);
            }
        }
        __syncthreads();
    }

    // ---- store t (f32) ----
    wmma::store_matrix_sync(t32 + mtile * 16 * 64 + nbase,      acc[0], 64, wmma::mem_row_major);
    wmma::store_matrix_sync(t32 + mtile * 16 * 64 + nbase + 16, acc[1], 64, wmma::mem_row_major);
    __syncthreads();

    // ---- t + bias -> hi/lo (in place over t32); lw split into R1 ----
    {
        int cb = (tid & 3) * 16;
        float tv[16];
        const float4* bp = (const float4*)(bias + cb);
        float4 b0 = __ldg(bp), b1 = __ldg(bp + 1), b2 = __ldg(bp + 2), b3 = __ldg(bp + 3);
        float bb[16] = {b0.x, b0.y, b0.z, b0.w, b1.x, b1.y, b1.z, b1.w,
                        b2.x, b2.y, b2.z, b2.w, b3.x, b3.y, b3.z, b3.w};
#pragma unroll
        for (int j = 0; j < 16; j++) tv[j] = t32[row * 64 + cb + j] + bb[j];
        float lwv[16];
        const float4* lp = (const float4*)(LW + row * 64 + cb);
        float4 l0 = __ldg(lp), l1 = __ldg(lp + 1), l2 = __ldg(lp + 2), l3 = __ldg(lp + 3);
        float ll[16] = {l0.x, l0.y, l0.z, l0.w, l1.x, l1.y, l1.z, l1.w,
                        l2.x, l2.y, l2.z, l2.w, l3.x, l3.y, l3.z, l3.w};
#pragma unroll
        for (int j = 0; j < 16; j++) lwv[j] = ll[j];
        __syncthreads();   // all t32 reads done before overwrite
#pragma unroll
        for (int j = 0; j < 16; j++) {
            __half h, l; split2(tv[j], h, l);
            t_hi[row * 64 + cb + j] = h;
            t_lo[row * 64 + cb + j] = l;
            __half lh, llo; split2(lwv[j], lh, llo);
            lw_hi[row * 72 + cb + j] = lh;
            lw_lo[row * 72 + cb + j] = llo;
        }
    }
    __syncthreads();

    // ---- lin mma ----
    wmma::fragment<wmma::accumulator, 16, 16, 16, float> acc2[2];
    wmma::fill_fragment(acc2[0], 0.f);
    wmma::fill_fragment(acc2[1], 0.f);
#pragma unroll 1
    for (int kt = 0; kt < 64; kt += 16) {
        wmma::fragment<wmma::matrix_a, 16, 16, 16, __half, wmma::row_major> a_hi, a_lo;
        wmma::load_matrix_sync(a_hi, t_hi + mtile * 16 * 64 + kt, 64);
        wmma::load_matrix_sync(a_lo, t_lo + mtile * 16 * 64 + kt, 64);
#pragma unroll
        for (int t = 0; t < 2; t++) {
            int n0 = nbase + t * 16;
            wmma::fragment<wmma::matrix_b, 16, 16, 16, __half, wmma::col_major> b_hi, b_lo;
            wmma::load_matrix_sync(b_hi, lw_hi + n0 * 72 + kt, 72);
            wmma::load_matrix_sync(b_lo, lw_lo + n0 * 72 + kt, 72);
            wmma::mma_sync(acc2[t], a_hi, b_hi, acc2[t]);
            wmma::mma_sync(acc2[t], a_hi, b_lo, acc2[t]);
            wmma::mma_sync(acc2[t], a_lo, b_hi, acc2[t]);
        }
    }
    __syncthreads();   // t_hi/t_lo reads done before t32 overwrite
    wmma::store_matrix_sync(t32 + mtile * 16 * 64 + nbase,      acc2[0], 64, wmma::mem_row_major);
    wmma::store_matrix_sync(t32 + mtile * 16 * 64 + nbase + 16, acc2[1], 64, wmma::mem_row_major);
    __syncthreads();

    // ---- +lb, relu, store f32 + split halves for next layer ----
    {
        int nn = bm + row;
        if (nn < n) {
            int cb = (tid & 3) * 16;
            const float4* lbp = (const float4*)(lb + cb);
            float4 l0 = __ldg(lbp), l1 = __ldg(lbp + 1), l2 = __ldg(lbp + 2), l3 = __ldg(lbp + 3);
            float lbv[16] = {l0.x, l0.y, l0.z, l0.w, l1.x, l1.y, l1.z, l1.w,
                             l2.x, l2.y, l2.z, l2.w, l3.x, l3.y, l3.z, l3.w};
#pragma unroll
            for (int q = 0; q < 4; q++) {
                float vv[4];
#pragma unroll
                for (int j = 0; j < 4; j++)
                    vv[j] = fmaxf(t32[row * 64 + cb + q * 4 + j] + lbv[q * 4 + j], 0.f);
                float4 o = make_float4(vv[0], vv[1], vv[2], vv[3]);
                *(float4*)(xo + nn * 64 + cb + q * 4) = o;
#pragma unroll
                for (int j = 0; j < 4; j++) {
                    __half h, l; split2(vv[j], h, l);
                    g_xh[nn * 128 + cb + q * 4 + j] = h;
                    g_xh[nn * 128 + 64 + cb + q * 4 + j] = l;
                }
            }
        }
    }
}

// ---------------- pooling: segmented (batch sorted) + final MLP ----------------
__global__ __launch_bounds__(256) void k_pool(const int* __restrict__ batch, int n) {
    int tid = threadIdx.x;
    int d = tid & 63, sub = tid >> 6;
    int base = blockIdx.x * 128 + sub * 32;
    float run = 0.f, runc = 0.f;
    int cur = -1;
    int lim = min(32, n - base);
    for (int j = 0; j < lim; j++) {
        int nn = base + j;
        int g = batch[nn];
        if (g != cur) {
            if (cur >= 0) {
                atomicAdd(&g_pool[cur * 64 + d], run);
                if (d == 0) atomicAdd(&g_cnt[cur], runc);
            }
            run = 0.f; runc = 0.f; cur = g;
        }
        run += g_x1[nn * 64 + d];
        runc += 1.f;
    }
    if (cur >= 0) {
        atomicAdd(&g_pool[cur * 64 + d], run);
        if (d == 0) atomicAdd(&g_cnt[cur], runc);
    }
}

__global__ void k_mlp(const float* __restrict__ w1, const float* __restrict__ b1,
                      const float* __restrict__ w2, const float* __restrict__ b2,
                      float* __restrict__ out) {
    __shared__ float gs[64][65];
    __shared__ float hs[64][65];
    int tid = threadIdx.x;
    for (int i = tid; i < GNUM * 64; i += 128) {
        int g = i >> 6;
        float c = fmaxf(g_cnt[g], 1.f);
        gs[g][i & 63] = g_pool[i] / c;
    }
    __syncthreads();
    for (int i = tid; i < GNUM * 64; i += 128) {
        int g = i >> 6, k = i & 63;
        float acc = b1[k];
#pragma unroll
        for (int d = 0; d < 64; d++) acc = fmaf(gs[g][d], w1[k * 64 + d], acc);
        hs[g][k] = fmaxf(acc, 0.f);
    }
    __syncthreads();
    for (int i = tid; i < GNUM * 16; i += 128) {
        int g = i >> 4, k = i & 15;
        float acc = b2[k];
#pragma unroll
        for (int d = 0; d < 64; d++) acc = fmaf(hs[g][d], w2[k * 64 + d], acc);
        out[i] = acc;
    }
}

// ---------------- launch ----------------
extern "C" void kernel_launch(void* const* d_in, const int* in_sizes, int n_in,
                              void* d_out, int out_size) {
    const float* x      = (const float*)d_in[0];
    const int*   ei     = (const int*)d_in[1];
    const int*   batch  = (const int*)d_in[2];
    const float* pre_w  = (const float*)d_in[3];
    const float* pre_b  = (const float*)d_in[4];
    const float* post_w = (const float*)d_in[5];
    const float* post_b = (const float*)d_in[6];
    const float* lin_w  = (const float*)d_in[7];
    const float* lin_b  = (const float*)d_in[8];
    const float* mlp_w1 = (const float*)d_in[9];
    const float* mlp_b1 = (const float*)d_in[10];
    const float* mlp_w2 = (const float*)d_in[11];
    const float* mlp_b2 = (const float*)d_in[12];
    float* out = (float*)d_out;

    int N = in_sizes[0] / 64;
    int E = in_sizes[1] / 2;
    if (N > NMAX) N = NMAX;
    if (E > EMAX) E = EMAX;

    int nb = (N + 1023) / 1024;

    k_zero<<<(N + 255) / 256, 256>>>(N);
    k_deg<<<(E + 255) / 256, 256>>>(ei, E);
    k_scan1<<<nb, 1024>>>(N);
    k_scan2<<<1, 32>>>(nb);
    k_scan3<<<nb, 1024>>>(N);
    k_csr<<<(E + 255) / 256, 256>>>(ei, E);
    k_stat<<<(N + 255) / 256, 256>>>(N);
    k_xsplit<<<(N * 64 + 255) / 256, 256>>>(x, N);
    k_wsplit<<<(3 * 64 * 832 + 255) / 256, 256>>>(post_w);

    int gpre = (N + 31) / 32;
    int gpost = (N + 63) / 64;
    int gagg = (N * 32 + 255) / 256;

    // device pointer to g_wh layer blocks is implicit via index math inside kernel;
    // pass per-layer base by pointer arithmetic on the device symbol is not possible
    // host-side, so k_postlin receives the layer's Wh base via g_wh + offset resolved
    // on device: we pass the layer index packed in the pointer? No — use cudaGetSymbolAddress-free
    // approach: k_postlin takes layer offset as pointer into g_wh computed on device is
    // not needed; instead pass layer index via outsel encoding? Simplest: pass Wh as
    // the device-global base plus offset using a small helper: we pass the layer index.
    for (int l = 0; l < 3; l++) {
        int insel = (l == 0) ? 0 : ((l == 1) ? 1 : 2);
        int outsel = (l == 1) ? 2 : 1;
        k_pre<<<gpre, 128>>>(insel, x, pre_w + l * 64 * 128, pre_b + l * 64, N);
        k_aggr<<<gagg, 256>>>(N);
        // g_wh is a device symbol; obtain its address once
        static __half* wh_base = nullptr;
        if (!wh_base) cudaGetSymbolAddress((void**)&wh_base, g_wh);
        k_postlin<<<gpost, 256>>>(wh_base + (size_t)l * 2 * 64 * 832,
                                  post_b + l * 64,
                                  lin_w + l * 64 * 64, lin_b + l * 64, outsel, N);
    }

    k_pool<<<((N + 127) / 128), 256>>>(batch, N);
    k_mlp<<<1, 128>>>(mlp_w1, mlp_b1, mlp_w2, mlp_b2, out);
}